// round 11
// baseline (speedup 1.0000x reference)
#include <cuda_runtime.h>
#include <cstdint>
#include <cfloat>

// Problem constants
#define Bz 16
#define Cz 64
#define Nz 4096
#define Qz 8
#define Kz 8192
#define BNz (Bz*Nz)          // 65536 points
#define TM 128               // points per block
#define TN 128               // codes per tile
#define NTILES (Kz/TN)       // 64
#define NBLK (BNz/TM)        // 512 blocks per quantizer step

// Scratch (no allocations allowed)
__device__ float g_res[BNz*Cz];          // residual, [point][c], 16 MB
__device__ float g_cbT[Qz*Cz*Kz];        // codebook transposed [q][c][k], 16 MB
__device__ float g_cbsq[Qz*Kz];          // |cb|^2 per code
__device__ float g_losspart[Qz*NBLK];    // per-block loss partials

static __device__ __forceinline__ void cp_async16(uint32_t s, const void* g) {
    asm volatile("cp.async.cg.shared.global [%0], [%1], 16;\n" :: "r"(s), "l"(g));
}

// ---------------------------------------------------------------------------
__global__ void cbsq_kernel(const float* __restrict__ cb) {
    int i = blockIdx.x * blockDim.x + threadIdx.x;   // q*K + k
    if (i >= Qz*Kz) return;
    const float4* row = (const float4*)(cb + (size_t)i * Cz);
    float s = 0.f;
#pragma unroll
    for (int j = 0; j < Cz/4; ++j) {
        float4 v = row[j];
        s += v.x*v.x + v.y*v.y + v.z*v.z + v.w*v.w;
    }
    g_cbsq[i] = s;
}

// codebook transpose: [q][k][c] -> [q][c][k]   (32x32 smem tiles)
__global__ void transpose_cb_kernel(const float* __restrict__ cb) {
    __shared__ float sm[32][33];
    const int q  = blockIdx.z;
    const int kt = blockIdx.x * 32;
    const int ct = blockIdx.y * 32;
    const float* src = cb + (size_t)q * Kz * Cz;
    float* dst = g_cbT + (size_t)q * Cz * Kz;
#pragma unroll
    for (int j = 0; j < 4; ++j) {
        int k = kt + threadIdx.y + j * 8;
        sm[threadIdx.y + j * 8][threadIdx.x] = src[(size_t)k * Cz + ct + threadIdx.x];
    }
    __syncthreads();
#pragma unroll
    for (int j = 0; j < 4; ++j) {
        int c = ct + threadIdx.y + j * 8;
        dst[(size_t)c * Kz + kt + threadIdx.x] = sm[threadIdx.x][threadIdx.y + j * 8];
    }
}

// residual := x transposed to point-major [B*N, C]
__global__ void init_kernel(const float* __restrict__ x) {
    int i = blockIdx.x * blockDim.x + threadIdx.x;   // p*C + c
    if (i >= BNz*Cz) return;
    int p = i >> 6, c = i & 63;
    int b = p >> 12, n = p & (Nz - 1);
    g_res[i] = x[((size_t)b * Cz + c) * Nz + n];
}

// ---------------------------------------------------------------------------
// One RVQ step. 8 points x 8 codes register tile, TM=128/block=256 so each
// 32KB code tile amortizes over 2M FMA. Code tiles double-buffered via
// cp.async (LDGSTS) so tile t+1 streams in during compute of tile t.
// 2 CTAs/SM (96KB smem, <=128 regs) -> 16 warps/SM.
__global__ void __launch_bounds__(256, 2) rvq_step(
    const float* __restrict__ cb,      // this quantizer's codebook [K][C] (epilogue)
    const float* __restrict__ cbT,     // this quantizer's codebook [C][K]
    int q,
    float* __restrict__ out_idx)       // may be null
{
    __shared__ float s_resT[Cz][TM];   // residual tile, transposed  (32 KB)
    __shared__ float s_cb[2][Cz][TN];  // code tiles, c-major        (2 x 32 KB)

    const int tid = threadIdx.x;
    const int tx  = tid & 15;          // code-group  (16) -> codes jg*64 + tx*4 + e
    const int ty  = tid >> 4;          // point-group (16) -> points ty*8 + i
    const int pbase = blockIdx.x * TM;

    const float* cbsq = g_cbsq + (size_t)q * Kz;

    // ---- load residual tile (transpose into smem). 2 threads per point row.
    {
        int p  = tid & 127;
        int ch = tid >> 7;             // 0/1 -> c 0..31 / 32..63
        const float4* src = (const float4*)(g_res + ((size_t)(pbase + p)) * Cz + ch * 32);
#pragma unroll
        for (int i = 0; i < 8; ++i) {
            float4 v = src[i];
            int c0 = ch * 32 + i * 4;
            s_resT[c0+0][p] = v.x; s_resT[c0+1][p] = v.y;
            s_resT[c0+2][p] = v.z; s_resT[c0+3][p] = v.w;
        }
    }

    // ---- async prefetch of code tile t into buffer t&1 (8 x 16B per thread)
    const float4* srcT = (const float4*)cbT;     // [Cz][Kz/4] float4 rows
    uint32_t cb_smem0 = (uint32_t)__cvta_generic_to_shared(&s_cb[0][0][0]);
    uint32_t cb_smem1 = (uint32_t)__cvta_generic_to_shared(&s_cb[1][0][0]);

    {   // prefetch tile 0
        const float4* src = srcT;                // kbase 0 -> +0 float4
#pragma unroll
        for (int i = 0; i < 8; ++i) {
            int f = i * 256 + tid;               // 2048 float4 per tile
            int row = f >> 5, col4 = f & 31;     // 32 float4 per c-row
            cp_async16(cb_smem0 + f * 16, src + (size_t)row * (Kz/4) + col4);
        }
        asm volatile("cp.async.commit_group;\n");
    }

    float bestd[8];
    int   bestk[8];
#pragma unroll
    for (int i = 0; i < 8; ++i) { bestd[i] = FLT_MAX; bestk[i] = 0; }

    for (int t = 0; t < NTILES; ++t) {
        const int kbase = t * TN;
        // prefetch t+1 into the buffer freed by compute of t-1
        if (t + 1 < NTILES) {
            const float4* src = srcT + ((t + 1) * TN) / 4;
            uint32_t dstb = ((t + 1) & 1) ? cb_smem1 : cb_smem0;
#pragma unroll
            for (int i = 0; i < 8; ++i) {
                int f = i * 256 + tid;
                int row = f >> 5, col4 = f & 31;
                cp_async16(dstb + f * 16, src + (size_t)row * (Kz/4) + col4);
            }
            asm volatile("cp.async.commit_group;\n");
            asm volatile("cp.async.wait_group 1;\n");   // tile t resident
        } else {
            asm volatile("cp.async.wait_group 0;\n");
        }
        __syncthreads();

        // ---- 8 points x 8 codes register tile over c = 0..63
        const float (*cbt)[TN] = s_cb[t & 1];
        float acc[8][8];
#pragma unroll
        for (int i = 0; i < 8; ++i)
#pragma unroll
            for (int j = 0; j < 8; ++j) acc[i][j] = 0.f;

#pragma unroll 2
        for (int c = 0; c < Cz; ++c) {
            float4 r0 = *(const float4*)&s_resT[c][ty * 8];
            float4 r1 = *(const float4*)&s_resT[c][ty * 8 + 4];
            float4 b0 = *(const float4*)&cbt[c][tx * 4];
            float4 b1 = *(const float4*)&cbt[c][64 + tx * 4];
            float rv[8] = {r0.x, r0.y, r0.z, r0.w, r1.x, r1.y, r1.z, r1.w};
            float cv[8] = {b0.x, b0.y, b0.z, b0.w, b1.x, b1.y, b1.z, b1.w};
#pragma unroll
            for (int i = 0; i < 8; ++i)
#pragma unroll
                for (int j = 0; j < 8; ++j)
                    acc[i][j] = fmaf(rv[i], cv[j], acc[i][j]);
        }

        // ---- dist = |cb|^2 - 2*dot ; running argmin
        // Within a thread k strictly increases over (t, jg, e): strict '<'
        // keeps the lowest tied index automatically.
#pragma unroll
        for (int jg = 0; jg < 2; ++jg) {
            float4 v = *(const float4*)&cbsq[kbase + jg * 64 + tx * 4];
            float cbs[4] = {v.x, v.y, v.z, v.w};
#pragma unroll
            for (int i = 0; i < 8; ++i) {
#pragma unroll
                for (int e = 0; e < 4; ++e) {
                    float d = fmaf(-2.f, acc[i][jg*4+e], cbs[e]);
                    int   k = kbase + jg * 64 + tx * 4 + e;
                    if (d < bestd[i]) { bestd[i] = d; bestk[i] = k; }
                }
            }
        }
        __syncthreads();   // compute of t done everywhere before t+2 prefetch
    }

    // ---- reduce across the 16 tx-threads (xor butterfly stays in ty-half)
#pragma unroll
    for (int off = 1; off < 16; off <<= 1) {
#pragma unroll
        for (int i = 0; i < 8; ++i) {
            float od = __shfl_xor_sync(0xffffffffu, bestd[i], off);
            int   ok = __shfl_xor_sync(0xffffffffu, bestk[i], off);
            if (od < bestd[i] || (od == bestd[i] && ok < bestk[i])) {
                bestd[i] = od; bestk[i] = ok;
            }
        }
    }

    int*   s_k = (int*)&s_cb[0][0][0];     // 128 ints (tile buffers now free)
    float* s_l = &s_cb[0][2][0];           // 8 floats for warp partials
    if (tx == 0) {
#pragma unroll
        for (int i = 0; i < 8; ++i) s_k[ty * 8 + i] = bestk[i];
    }
    __syncthreads();

    // ---- fused residual update + loss partial (TM*Cz = 8192 elems)
    float lsum = 0.f;
#pragma unroll
    for (int e0 = 0; e0 < TM * Cz; e0 += 256) {
        int e = e0 + tid;
        int p = e >> 6, c = e & 63;
        float code = cb[(size_t)s_k[p] * Cz + c];
        float rnew = g_res[(size_t)pbase * Cz + e] - code;
        g_res[(size_t)pbase * Cz + e] = rnew;
        lsum += rnew * rnew;
    }
#pragma unroll
    for (int off = 16; off > 0; off >>= 1)
        lsum += __shfl_xor_sync(0xffffffffu, lsum, off);
    if ((tid & 31) == 0) s_l[tid >> 5] = lsum;
    __syncthreads();
    if (tid == 0) {
        float s = 0.f;
#pragma unroll
        for (int w = 0; w < 8; ++w) s += s_l[w];
        g_losspart[q * NBLK + blockIdx.x] = s;
    }

    if (out_idx != nullptr && tid < TM)
        out_idx[(size_t)(pbase + tid) * Qz + q] = (float)s_k[tid];
}

// ---------------------------------------------------------------------------
// quantized = x - final residual, back in [B, C, N] layout
__global__ void final_kernel(const float* __restrict__ x, float* __restrict__ out) {
    int i = blockIdx.x * blockDim.x + threadIdx.x;
    if (i >= Bz*Cz*Nz) return;
    int n = i & (Nz - 1);
    int c = (i >> 12) & 63;
    int b = i >> 18;
    int p = (b << 12) | n;
    out[i] = x[i] - g_res[(size_t)p * Cz + c];
}

// mean loss: deterministic single-block reduction over Q*NBLK partials
__global__ void loss_kernel(float* __restrict__ out_loss) {
    __shared__ float sm[256];
    float s = 0.f;
    for (int i = threadIdx.x; i < Qz * NBLK; i += 256) s += g_losspart[i];
    sm[threadIdx.x] = s;
    __syncthreads();
    for (int w = 128; w > 0; w >>= 1) {
        if (threadIdx.x < w) sm[threadIdx.x] += sm[threadIdx.x + w];
        __syncthreads();
    }
    if (threadIdx.x == 0)
        *out_loss = sm[0] / ((float)Qz * (float)BNz * (float)Cz);
}

// ---------------------------------------------------------------------------
extern "C" void kernel_launch(void* const* d_in, const int* in_sizes, int n_in,
                              void* d_out, int out_size) {
    const float* x  = (const float*)d_in[0];   // [B, C, N]
    const float* cb = (const float*)d_in[1];   // [Q, K, C]
    float* out = (float*)d_out;

    const int OUTQ = Bz * Cz * Nz;                       // 4,194,304
    const bool full = out_size >= OUTQ + BNz * Qz + 1;   // quantized + indices + loss
    float* idx_out  = full ? out + OUTQ : nullptr;
    float* loss_out = full ? out + OUTQ + BNz * Qz : nullptr;

    cbsq_kernel<<<(Qz*Kz + 255) / 256, 256>>>(cb);
    {
        dim3 g(Kz/32, Cz/32, Qz), b(32, 8);
        transpose_cb_kernel<<<g, b>>>(cb);
    }
    init_kernel<<<(BNz*Cz + 255) / 256, 256>>>(x);

    float* cbT_base;
    cudaGetSymbolAddress((void**)&cbT_base, g_cbT);
    for (int q = 0; q < Qz; ++q)
        rvq_step<<<NBLK, 256>>>(cb + (size_t)q * Kz * Cz,
                                cbT_base + (size_t)q * Cz * Kz, q, idx_out);
    final_kernel<<<(OUTQ + 255) / 256, 256>>>(x, out);
    if (full) loss_kernel<<<1, 256>>>(loss_out);
}

// round 13
// speedup vs baseline: 1.3938x; 1.3938x over previous
#include <cuda_runtime.h>
#include <cstdint>
#include <cfloat>
#include <climits>

// Problem constants
#define Bz 16
#define Cz 64
#define Nz 4096
#define Qz 8
#define Kz 8192
#define BNz (Bz*Nz)          // 65536 points
#define TM 64                // points per block
#define TN 128               // codes per tile
#define NTILES (Kz/TN)       // 64
#define NBLK (BNz/TM)        // 1024 blocks per quantizer step

// Scratch (no allocations allowed)
__device__ float    g_res[BNz*Cz];       // residual, [point][c], 16 MB
__device__ uint32_t g_cb8T[Qz*16*Kz];    // int8x4-packed codebook, [q][c4][k], 4 MB
__device__ float    g_m2sc[Qz*Kz];       // -2 * per-code int8 scale
__device__ float    g_cbsq[Qz*Kz];       // |cb|^2 per code (exact fp32)
__device__ float    g_maxsc[Qz];         // max per-code scale   (atomicMax, monotone)
__device__ float    g_maxL1[Qz];         // max per-code quantized L1 norm
__device__ float    g_losspart[Qz*NBLK]; // per-block loss partials

static __device__ __forceinline__ void cp_async16(uint32_t s, const void* g) {
    asm volatile("cp.async.cg.shared.global [%0], [%1], 16;\n" :: "r"(s), "l"(g));
}

// ---------------------------------------------------------------------------
__global__ void cbsq_kernel(const float* __restrict__ cb) {
    int i = blockIdx.x * blockDim.x + threadIdx.x;   // q*K + k
    if (i >= Qz*Kz) return;
    const float4* row = (const float4*)(cb + (size_t)i * Cz);
    float s = 0.f;
#pragma unroll
    for (int j = 0; j < Cz/4; ++j) {
        float4 v = row[j];
        s += v.x*v.x + v.y*v.y + v.z*v.z + v.w*v.w;
    }
    g_cbsq[i] = s;
}

// int8-quantize codebook (per-code scale) into c4-major g_cb8T[q][c4][k];
// also per-quantizer maxima for the certified error bound.
__global__ void quant_cb_kernel(const float* __restrict__ cb) {
    const int tid = threadIdx.x;               // 64 threads = 64 codes
    const int q   = blockIdx.y;
    const int k   = blockIdx.x * 64 + tid;
    const float4* row = (const float4*)(cb + ((size_t)q * Kz + k) * Cz);
    float4 v[16];
    float m = 0.f;
#pragma unroll
    for (int j = 0; j < 16; ++j) {
        v[j] = row[j];
        m = fmaxf(m, fmaxf(fmaxf(fabsf(v[j].x), fabsf(v[j].y)),
                           fmaxf(fabsf(v[j].z), fabsf(v[j].w))));
    }
    float inv = (m > 1e-30f) ? (127.f / m) : 0.f;
    float sc  = m * (1.f / 127.f);
    g_m2sc[(size_t)q * Kz + k] = -2.f * sc;
    int sabs8 = 0;
#pragma unroll
    for (int j = 0; j < 16; ++j) {
        float f[4] = {v[j].x, v[j].y, v[j].z, v[j].w};
        uint32_t pk = 0;
#pragma unroll
        for (int e = 0; e < 4; ++e) {
            int iv = __float2int_rn(f[e] * inv);
            iv = max(-127, min(127, iv));
            sabs8 += abs(iv);
            pk |= ((uint32_t)iv & 0xFF) << (e * 8);
        }
        g_cb8T[((size_t)q * 16 + j) * Kz + k] = pk;
    }
    // monotone, input-determined -> deterministic across graph replays
    atomicMax((int*)&g_maxsc[q], __float_as_int(sc));
    atomicMax((int*)&g_maxL1[q], __float_as_int(sc * (float)sabs8));
}

// residual := x transposed to point-major [B*N, C]
__global__ void init_kernel(const float* __restrict__ x) {
    int i = blockIdx.x * blockDim.x + threadIdx.x;   // p*C + c
    if (i >= BNz*Cz) return;
    int p = i >> 6, c = i & 63;
    int b = p >> 12, n = p & (Nz - 1);
    g_res[i] = x[((size_t)b * Cz + c) * Nz + n];
}

// ---------------------------------------------------------------------------
// One RVQ step, certified int8 screening:
//  Pass A: dp4a distances over all K -> per-point approx min m
//  margin = m + 2B with rigorous quantization-error bound B
//  Pass B: identical dp4a distances; candidates within margin get exact
//          fp32 rerank (same fmaf chain as the fp32 kernel) -> exact argmin.
__global__ void __launch_bounds__(128, 3) rvq_step_i8(
    const float* __restrict__ cb,      // this quantizer's fp32 codebook [K][C]
    int q,
    float* __restrict__ out_idx)       // may be null
{
    __shared__ float    s_resf[TM][68];     // fp32 residual (pad 68)  17 KB
    __shared__ uint32_t s_res8[16][TM];     // int8x4 residual          4 KB
    __shared__ float    s_sr[TM];           // per-point int8 scale
    __shared__ float    s_sabs[TM];         // per-point sum |r|
    __shared__ float    s_mg[TM];           // per-point margin
    __shared__ uint32_t s_cb8[2][16][TN];   // code tiles               16 KB
    __shared__ int      s_k[TM];
    __shared__ float    s_l[4];

    const int tid = threadIdx.x;
    const int tx  = tid & 15;          // code-group (16)
    const int ty  = tid >> 4;          // point-group (8)
    const int pbase = blockIdx.x * TM;

    const float*    cbsq = g_cbsq + (size_t)q * Kz;
    const float*    m2sc = g_m2sc + (size_t)q * Kz;
    const uint32_t* cb8  = g_cb8T + (size_t)q * 16 * Kz;

    // ---- load fp32 residual tile + quantize to int8 (one thread per point)
    if (tid < TM) {
        const float4* src = (const float4*)(g_res + ((size_t)(pbase + tid)) * Cz);
        float4 v[16];
        float m = 0.f, sa = 0.f;
#pragma unroll
        for (int j = 0; j < 16; ++j) {
            v[j] = src[j];
            ((float4*)&s_resf[tid][0])[j] = v[j];
            m  = fmaxf(m, fmaxf(fmaxf(fabsf(v[j].x), fabsf(v[j].y)),
                                fmaxf(fabsf(v[j].z), fabsf(v[j].w))));
            sa += fabsf(v[j].x) + fabsf(v[j].y) + fabsf(v[j].z) + fabsf(v[j].w);
        }
        float inv = (m > 1e-30f) ? (127.f / m) : 0.f;
        s_sr[tid]   = m * (1.f / 127.f);
        s_sabs[tid] = sa;
#pragma unroll
        for (int j = 0; j < 16; ++j) {
            float f[4] = {v[j].x, v[j].y, v[j].z, v[j].w};
            uint32_t pk = 0;
#pragma unroll
            for (int e = 0; e < 4; ++e) {
                int iv = __float2int_rn(f[e] * inv);
                iv = max(-127, min(127, iv));
                pk |= ((uint32_t)iv & 0xFF) << (e * 8);
            }
            s_res8[j][tid] = pk;
        }
    }

    uint32_t cbsm0 = (uint32_t)__cvta_generic_to_shared(&s_cb8[0][0][0]);
    uint32_t cbsm1 = (uint32_t)__cvta_generic_to_shared(&s_cb8[1][0][0]);

#define PREFETCH_TILE(TT, DSTB) do {                                          \
        const uint32_t* _src = cb8 + (TT) * TN;                               \
        _Pragma("unroll")                                                     \
        for (int _i = 0; _i < 4; ++_i) {                                      \
            int _f = _i * 128 + tid;                                          \
            int _row = _f >> 5, _col4 = _f & 31;                              \
            cp_async16((DSTB) + _f * 16, _src + (size_t)_row * Kz + _col4*4); \
        }                                                                     \
        asm volatile("cp.async.commit_group;\n");                             \
    } while (0)

    PREFETCH_TILE(0, cbsm0);
    __syncthreads();

    float srr[8];
#pragma unroll
    for (int i = 0; i < 8; ++i) srr[i] = s_sr[ty * 8 + i];

    // ================= PASS A: approximate min =================
    float minapp[8];
#pragma unroll
    for (int i = 0; i < 8; ++i) minapp[i] = FLT_MAX;

    for (int t = 0; t < NTILES; ++t) {
        const int kbase = t * TN;
        if (t + 1 < NTILES) {
            PREFETCH_TILE(t + 1, ((t + 1) & 1) ? cbsm1 : cbsm0);
            asm volatile("cp.async.wait_group 1;\n");
        } else {
            asm volatile("cp.async.wait_group 0;\n");
        }
        __syncthreads();

        const uint32_t (*cbt)[TN] = s_cb8[t & 1];
        int acc[8][8];
#pragma unroll
        for (int i = 0; i < 8; ++i)
#pragma unroll
            for (int j = 0; j < 8; ++j) acc[i][j] = 0;
#pragma unroll 4
        for (int c4 = 0; c4 < 16; ++c4) {
            uint4 ra0 = *(const uint4*)&s_res8[c4][ty * 8];
            uint4 ra1 = *(const uint4*)&s_res8[c4][ty * 8 + 4];
            uint4 cc0 = *(const uint4*)&cbt[c4][tx * 4];
            uint4 cc1 = *(const uint4*)&cbt[c4][64 + tx * 4];
            uint32_t rr[8] = {ra0.x, ra0.y, ra0.z, ra0.w, ra1.x, ra1.y, ra1.z, ra1.w};
            uint32_t cc[8] = {cc0.x, cc0.y, cc0.z, cc0.w, cc1.x, cc1.y, cc1.z, cc1.w};
#pragma unroll
            for (int i = 0; i < 8; ++i)
#pragma unroll
                for (int j = 0; j < 8; ++j)
                    acc[i][j] = __dp4a((int)rr[i], (int)cc[j], acc[i][j]);
        }

        float4 m0 = __ldg((const float4*)&m2sc[kbase + tx * 4]);
        float4 m1 = __ldg((const float4*)&m2sc[kbase + 64 + tx * 4]);
        float4 c0 = __ldg((const float4*)&cbsq[kbase + tx * 4]);
        float4 c1 = __ldg((const float4*)&cbsq[kbase + 64 + tx * 4]);
        float msv[8] = {m0.x, m0.y, m0.z, m0.w, m1.x, m1.y, m1.z, m1.w};
        float cqv[8] = {c0.x, c0.y, c0.z, c0.w, c1.x, c1.y, c1.z, c1.w};
#pragma unroll
        for (int i = 0; i < 8; ++i)
#pragma unroll
            for (int j = 0; j < 8; ++j)
                minapp[i] = fminf(minapp[i],
                                  fmaf(srr[i] * msv[j], (float)acc[i][j], cqv[j]));
        __syncthreads();
    }

    // min across the 16 tx-threads
#pragma unroll
    for (int off = 1; off < 16; off <<= 1)
#pragma unroll
        for (int i = 0; i < 8; ++i)
            minapp[i] = fminf(minapp[i], __shfl_xor_sync(0xffffffffu, minapp[i], off));

    // rigorous margin: |d_exact - d_approx| <= B
    if (tx == 0) {
        float msc = g_maxsc[q], mL1 = g_maxL1[q];
#pragma unroll
        for (int i = 0; i < 8; ++i) {
            int p = ty * 8 + i;
            float er = 0.51f * s_sr[p];      // residual per-element quant error
            float ec = 0.51f * msc;          // code per-element quant error
            float B = 2.f * (er * mL1 + ec * s_sabs[p] + 128.f * er * ec);
            s_mg[p] = minapp[i] + 2.1f * B + 0.05f + 1e-3f * fabsf(minapp[i]);
        }
    }
    __syncthreads();

    float mgr[8];
#pragma unroll
    for (int i = 0; i < 8; ++i) mgr[i] = s_mg[ty * 8 + i];

    // ================= PASS B: margin test + exact rerank =================
    float bd[8]; int bk[8];
#pragma unroll
    for (int i = 0; i < 8; ++i) { bd[i] = FLT_MAX; bk[i] = INT_MAX; }

    PREFETCH_TILE(0, cbsm0);

    for (int t = 0; t < NTILES; ++t) {
        const int kbase = t * TN;
        if (t + 1 < NTILES) {
            PREFETCH_TILE(t + 1, ((t + 1) & 1) ? cbsm1 : cbsm0);
            asm volatile("cp.async.wait_group 1;\n");
        } else {
            asm volatile("cp.async.wait_group 0;\n");
        }
        __syncthreads();

        const uint32_t (*cbt)[TN] = s_cb8[t & 1];
        int acc[8][8];
#pragma unroll
        for (int i = 0; i < 8; ++i)
#pragma unroll
            for (int j = 0; j < 8; ++j) acc[i][j] = 0;
#pragma unroll 4
        for (int c4 = 0; c4 < 16; ++c4) {
            uint4 ra0 = *(const uint4*)&s_res8[c4][ty * 8];
            uint4 ra1 = *(const uint4*)&s_res8[c4][ty * 8 + 4];
            uint4 cc0 = *(const uint4*)&cbt[c4][tx * 4];
            uint4 cc1 = *(const uint4*)&cbt[c4][64 + tx * 4];
            uint32_t rr[8] = {ra0.x, ra0.y, ra0.z, ra0.w, ra1.x, ra1.y, ra1.z, ra1.w};
            uint32_t cc[8] = {cc0.x, cc0.y, cc0.z, cc0.w, cc1.x, cc1.y, cc1.z, cc1.w};
#pragma unroll
            for (int i = 0; i < 8; ++i)
#pragma unroll
                for (int j = 0; j < 8; ++j)
                    acc[i][j] = __dp4a((int)rr[i], (int)cc[j], acc[i][j]);
        }

        float4 m0 = __ldg((const float4*)&m2sc[kbase + tx * 4]);
        float4 m1 = __ldg((const float4*)&m2sc[kbase + 64 + tx * 4]);
        float4 c0 = __ldg((const float4*)&cbsq[kbase + tx * 4]);
        float4 c1 = __ldg((const float4*)&cbsq[kbase + 64 + tx * 4]);
        float msv[8] = {m0.x, m0.y, m0.z, m0.w, m1.x, m1.y, m1.z, m1.w};
        float cqv[8] = {c0.x, c0.y, c0.z, c0.w, c1.x, c1.y, c1.z, c1.w};
#pragma unroll
        for (int i = 0; i < 8; ++i) {
#pragma unroll
            for (int j = 0; j < 8; ++j) {
                float d = fmaf(srr[i] * msv[j], (float)acc[i][j], cqv[j]);
                if (d <= mgr[i]) {                 // rare: exact fp32 rerank
                    int k = kbase + (j >> 2) * 64 + tx * 4 + (j & 3);
                    const int p = ty * 8 + i;
                    const float4* cp = (const float4*)(cb + (size_t)k * Cz);
                    float dot = 0.f;
#pragma unroll
                    for (int jj = 0; jj < 16; ++jj) {
                        float4 c = __ldg(cp + jj);
                        const float* rr4 = &s_resf[p][jj * 4];
                        dot = fmaf(rr4[0], c.x, dot);
                        dot = fmaf(rr4[1], c.y, dot);
                        dot = fmaf(rr4[2], c.z, dot);
                        dot = fmaf(rr4[3], c.w, dot);
                    }
                    float de = fmaf(-2.f, dot, __ldg(&cbsq[k]));
                    // k ascends within a thread -> strict '<' keeps lowest tie
                    if (de < bd[i]) { bd[i] = de; bk[i] = k; }
                }
            }
        }
        __syncthreads();
    }

    // exact (d,k) butterfly across the 16 tx-threads, tie -> lowest k
#pragma unroll
    for (int off = 1; off < 16; off <<= 1) {
#pragma unroll
        for (int i = 0; i < 8; ++i) {
            float od = __shfl_xor_sync(0xffffffffu, bd[i], off);
            int   ok = __shfl_xor_sync(0xffffffffu, bk[i], off);
            if (od < bd[i] || (od == bd[i] && ok < bk[i])) {
                bd[i] = od; bk[i] = ok;
            }
        }
    }
    if (tx == 0) {
#pragma unroll
        for (int i = 0; i < 8; ++i) s_k[ty * 8 + i] = bk[i];
    }
    __syncthreads();

    // ---- fused residual update + loss partial (TM*Cz = 4096 elems)
    float lsum = 0.f;
#pragma unroll
    for (int e0 = 0; e0 < TM * Cz; e0 += 128) {
        int e = e0 + tid;
        int p = e >> 6, c = e & 63;
        float code = cb[(size_t)s_k[p] * Cz + c];
        float rnew = s_resf[p][c] - code;
        g_res[(size_t)pbase * Cz + e] = rnew;
        lsum += rnew * rnew;
    }
#pragma unroll
    for (int off = 16; off > 0; off >>= 1)
        lsum += __shfl_xor_sync(0xffffffffu, lsum, off);
    if ((tid & 31) == 0) s_l[tid >> 5] = lsum;
    __syncthreads();
    if (tid == 0)
        g_losspart[q * NBLK + blockIdx.x] = s_l[0] + s_l[1] + s_l[2] + s_l[3];

    if (out_idx != nullptr && tid < TM)
        out_idx[(size_t)(pbase + tid) * Qz + q] = (float)s_k[tid];
#undef PREFETCH_TILE
}

// ---------------------------------------------------------------------------
// quantized = x - final residual, back in [B, C, N] layout
__global__ void final_kernel(const float* __restrict__ x, float* __restrict__ out) {
    int i = blockIdx.x * blockDim.x + threadIdx.x;
    if (i >= Bz*Cz*Nz) return;
    int n = i & (Nz - 1);
    int c = (i >> 12) & 63;
    int b = i >> 18;
    int p = (b << 12) | n;
    out[i] = x[i] - g_res[(size_t)p * Cz + c];
}

// mean loss: deterministic single-block reduction over Q*NBLK partials
__global__ void loss_kernel(float* __restrict__ out_loss) {
    __shared__ float sm[256];
    float s = 0.f;
    for (int i = threadIdx.x; i < Qz * NBLK; i += 256) s += g_losspart[i];
    sm[threadIdx.x] = s;
    __syncthreads();
    for (int w = 128; w > 0; w >>= 1) {
        if (threadIdx.x < w) sm[threadIdx.x] += sm[threadIdx.x + w];
        __syncthreads();
    }
    if (threadIdx.x == 0)
        *out_loss = sm[0] / ((float)Qz * (float)BNz * (float)Cz);
}

// ---------------------------------------------------------------------------
extern "C" void kernel_launch(void* const* d_in, const int* in_sizes, int n_in,
                              void* d_out, int out_size) {
    const float* x  = (const float*)d_in[0];   // [B, C, N]
    const float* cb = (const float*)d_in[1];   // [Q, K, C]
    float* out = (float*)d_out;

    const int OUTQ = Bz * Cz * Nz;                       // 4,194,304
    const bool full = out_size >= OUTQ + BNz * Qz + 1;   // quantized + indices + loss
    float* idx_out  = full ? out + OUTQ : nullptr;
    float* loss_out = full ? out + OUTQ + BNz * Qz : nullptr;

    cbsq_kernel<<<(Qz*Kz + 255) / 256, 256>>>(cb);
    {
        dim3 g(Kz/64, Qz);
        quant_cb_kernel<<<g, 64>>>(cb);
    }
    init_kernel<<<(BNz*Cz + 255) / 256, 256>>>(x);

    for (int q = 0; q < Qz; ++q)
        rvq_step_i8<<<NBLK, 128>>>(cb + (size_t)q * Kz * Cz, q, idx_out);
    final_kernel<<<(OUTQ + 255) / 256, 256>>>(x, out);
    if (full) loss_kernel<<<1, 256>>>(loss_out);
}